// round 15
// baseline (speedup 1.0000x reference)
#include <cuda_runtime.h>
#include <cuda_bf16.h>

// GradeWiseLinear: block-diagonal 16x16 linear (blocks 1,4,6,4,1) + bias.
// 2,097,152 rows x 16 fp32. 268 MB HBM traffic, pure streaming.
//
// R15: R14 structure (ld/st.global.v8.f32, half-row per lane, role=lane&1,
// one shfl_xor exchange, exact per-role blocks, ITERS=3) at 5 CTAs/SM:
// ALL weights (Q 4x4 rows too) read from smem at use; registers hold only
// load data + addressing. regs ~64 -> ~48, warps/SM 32 -> 40, in-flight
// bytes +25% (the validated DRAM% lever).

#define TPB 256
#define ITERS 3
#define FULLMASK 0xffffffffu

__global__ void __launch_bounds__(TPB, 5)
gradewise_linear_kernel(const float* __restrict__ x,
                        const float* __restrict__ w0, const float* __restrict__ b0,
                        const float* __restrict__ w1, const float* __restrict__ b1,
                        const float* __restrict__ w2, const float* __restrict__ b2,
                        const float* __restrict__ w3, const float* __restrict__ b3,
                        const float* __restrict__ w4, const float* __restrict__ b4,
                        float* __restrict__ out, int n_chunk)
{
    // sQ[role][4][4]: 4x4 block rows (W1 / W3), one LDS.128 per row
    // sH[role][3][8]: 3x6 half of W2, rows padded to 8 (2x LDS.128 per row)
    // sB[role][8]: [0..3] quad bias, [4..6] hex bias, [7] scalar bias
    // sws[role]: scalar weight (w0 / w4)
    __shared__ __align__(16) float sQ[2][4][4];
    __shared__ __align__(16) float sH[2][3][8];
    __shared__ __align__(16) float sB[2][8];
    __shared__ float sws[2];

    if (threadIdx.x == 0) {
        sws[0] = w0[0];  sB[0][7] = b0[0];
        sws[1] = w4[0];  sB[1][7] = b4[0];
#pragma unroll
        for (int i = 0; i < 16; i++) {
            sQ[0][i / 4][i % 4] = w1[i];
            sQ[1][i / 4][i % 4] = w3[i];
        }
#pragma unroll
        for (int j = 0; j < 4; j++)  { sB[0][j] = b1[j]; sB[1][j] = b3[j]; }
#pragma unroll
        for (int j = 0; j < 3; j++) {
#pragma unroll
            for (int i = 0; i < 6; i++) {
                sH[0][j][i] = w2[j * 6 + i];
                sH[1][j][i] = w2[(3 + j) * 6 + i];
            }
            sH[0][j][6] = 0.f; sH[0][j][7] = 0.f;
            sH[1][j][6] = 0.f; sH[1][j][7] = 0.f;
            sB[0][4 + j] = b2[j];
            sB[1][4 + j] = b2[3 + j];
        }
    }
    __syncthreads();

    const int role = threadIdx.x & 1;
    const float* Brole = sB[role];
    const float (*Qrole)[4] = sQ[role];
    const float (*Hrole)[8] = sH[role];
    const float ws = sws[role];

    const int base = blockIdx.x * (TPB * ITERS) + threadIdx.x;
    const bool full = (blockIdx.x + 1) * (TPB * ITERS) <= n_chunk;

    float a[ITERS][8];
    bool ok[ITERS];

    // ---- phase 1: issue all 256-bit loads (independent, MLP=ITERS) ----
#pragma unroll
    for (int t = 0; t < ITERS; t++) {
        int idx = base + t * TPB;
        ok[t] = full || (idx < n_chunk);
        const float* p = x + (size_t)idx * 8;
        if (ok[t]) {
            asm volatile(
                "ld.global.v8.f32 {%0,%1,%2,%3,%4,%5,%6,%7}, [%8];"
                : "=f"(a[t][0]), "=f"(a[t][1]), "=f"(a[t][2]), "=f"(a[t][3]),
                  "=f"(a[t][4]), "=f"(a[t][5]), "=f"(a[t][6]), "=f"(a[t][7])
                : "l"(p));
        } else {
#pragma unroll
            for (int i = 0; i < 8; i++) a[t][i] = 0.0f;
        }
    }

    // ---- phase 2: exchange + compute + store per sub-iteration ----
#pragma unroll
    for (int t = 0; t < ITERS; t++) {
        // even lane needs odd's a0..a2 (x8..x10); odd needs even's a5..a7.
        float s0 = role ? a[t][0] : a[t][5];
        float s1 = role ? a[t][1] : a[t][6];
        float s2 = role ? a[t][2] : a[t][7];
        float p0 = __shfl_xor_sync(FULLMASK, s0, 1);
        float p1 = __shfl_xor_sync(FULLMASK, s1, 1);
        float p2 = __shfl_xor_sync(FULLMASK, s2, 1);

        // scalar block
        float vsc = role ? a[t][7] : a[t][0];
        float sc = fmaf(ws, vsc, Brole[7]);

        // quad block inputs: role0 x1..x4 = a1..a4; role1 x11..x14 = a3..a6
        float q0 = role ? a[t][3] : a[t][1];
        float q1 = role ? a[t][4] : a[t][2];
        float q2 = role ? a[t][5] : a[t][3];
        float q3 = role ? a[t][6] : a[t][4];
        float qo[4];
#pragma unroll
        for (int j = 0; j < 4; j++) {
            // weight row from smem: 1 LDS.128, 2-address broadcast
            float4 qw = *reinterpret_cast<const float4*>(&Qrole[j][0]);
            float acc = Brole[j];
            acc = fmaf(qw.x, q0, acc);
            acc = fmaf(qw.y, q1, acc);
            acc = fmaf(qw.z, q2, acc);
            acc = fmaf(qw.w, q3, acc);
            qo[j] = acc;
        }

        // hex block inputs x5..x10:
        // role0: a5,a6,a7,p0,p1,p2   role1: p0,p1,p2,a0,a1,a2
        float h0 = role ? p0 : a[t][5];
        float h1 = role ? p1 : a[t][6];
        float h2 = role ? p2 : a[t][7];
        float h3 = role ? a[t][0] : p0;
        float h4 = role ? a[t][1] : p1;
        float h5 = role ? a[t][2] : p2;
        float ho[3];
#pragma unroll
        for (int j = 0; j < 3; j++) {
            float4 hw0 = *reinterpret_cast<const float4*>(&Hrole[j][0]);
            float4 hw1 = *reinterpret_cast<const float4*>(&Hrole[j][4]);
            float acc = Brole[4 + j];
            acc = fmaf(hw0.x, h0, acc);
            acc = fmaf(hw0.y, h1, acc);
            acc = fmaf(hw0.z, h2, acc);
            acc = fmaf(hw0.w, h3, acc);
            acc = fmaf(hw1.x, h4, acc);
            acc = fmaf(hw1.y, h5, acc);
            ho[j] = acc;
        }

        // output order: role0 {sc,qo0..3,ho0..2}; role1 {ho0..2,qo0..3,sc}
        float o0 = role ? ho[0] : sc;
        float o1 = role ? ho[1] : qo[0];
        float o2 = role ? ho[2] : qo[1];
        float o3 = role ? qo[0] : qo[2];
        float o4 = role ? qo[1] : qo[3];
        float o5 = role ? qo[2] : ho[0];
        float o6 = role ? qo[3] : ho[1];
        float o7 = role ? sc    : ho[2];

        if (ok[t]) {
            int idx = base + t * TPB;
            float* p = out + (size_t)idx * 8;
            asm volatile(
                "st.global.v8.f32 [%0], {%1,%2,%3,%4,%5,%6,%7,%8};"
                :: "l"(p),
                   "f"(o0), "f"(o1), "f"(o2), "f"(o3),
                   "f"(o4), "f"(o5), "f"(o6), "f"(o7)
                : "memory");
        }
    }
}

extern "C" void kernel_launch(void* const* d_in, const int* in_sizes, int n_in,
                              void* d_out, int out_size)
{
    const float* x  = (const float*)d_in[0];
    const float* w0 = (const float*)d_in[1];
    const float* b0 = (const float*)d_in[2];
    const float* w1 = (const float*)d_in[3];
    const float* b1 = (const float*)d_in[4];
    const float* w2 = (const float*)d_in[5];
    const float* b2 = (const float*)d_in[6];
    const float* w3 = (const float*)d_in[7];
    const float* b3 = (const float*)d_in[8];
    const float* w4 = (const float*)d_in[9];
    const float* b4 = (const float*)d_in[10];
    float* out = (float*)d_out;

    int n_chunk = in_sizes[0] / 8;          // 8-float half-rows
    int per_block = TPB * ITERS;
    int blocks = (n_chunk + per_block - 1) / per_block;

    gradewise_linear_kernel<<<blocks, TPB>>>(
        x, w0, b0, w1, b1, w2, b2, w3, b3, w4, b4, out, n_chunk);
}